// round 2
// baseline (speedup 1.0000x reference)
#include <cuda_runtime.h>
#include <math.h>

#define B 2
#define S 2048
#define D 512
#define H 8
#define DH 64
#define NB 10

// ---------------- scratch (static device allocations are allowed) ------------
__device__ float g_qp[B*S*D];
__device__ float g_kp[B*S*D];
__device__ float g_vp[B*S*D];
__device__ float g_coef[NB*B*H*S];                 // [n][b][h][s], pre-scaled by 0.1/8
__device__ float g_logits[(size_t)B*H*S*S];        // 268 MB
__device__ float g_attnv[B*S*D];                   // attn @ V, (b,s, h*64+d)

// ---------------- generic tiled GEMM:  C = A(MxK) * W(KxN) + bias ------------
__global__ void gemm_bias_kernel(const float* __restrict__ A, const float* __restrict__ W,
                                 const float* __restrict__ bias, float* __restrict__ C,
                                 int M, int N, int K)
{
    __shared__ float As[16*65];   // [k][m] padded
    __shared__ float Bs[16*64];   // [k][n]
    const int bm = blockIdx.y * 64, bn = blockIdx.x * 64;
    const int tid = threadIdx.x;
    const int tn = tid & 15, tq = tid >> 4;
    const int ar = tid >> 2, ac = (tid & 3) << 2;
    const int br = tid >> 4, bc = (tid & 15) << 2;
    float acc[4][4] = {};
    for (int k0 = 0; k0 < K; k0 += 16) {
        float4 a4 = *(const float4*)&A[(size_t)(bm + ar) * K + k0 + ac];
        As[(ac+0)*65 + ar] = a4.x; As[(ac+1)*65 + ar] = a4.y;
        As[(ac+2)*65 + ar] = a4.z; As[(ac+3)*65 + ar] = a4.w;
        float4 b4 = *(const float4*)&W[(size_t)(k0 + br) * N + bn + bc];
        *(float4*)&Bs[br*64 + bc] = b4;
        __syncthreads();
        #pragma unroll
        for (int k = 0; k < 16; k++) {
            float4 bv = *(const float4*)&Bs[k*64 + tn*4];
            float av[4];
            #pragma unroll
            for (int i = 0; i < 4; i++) av[i] = As[k*65 + tq*4 + i];
            #pragma unroll
            for (int i = 0; i < 4; i++) {
                acc[i][0] += av[i]*bv.x; acc[i][1] += av[i]*bv.y;
                acc[i][2] += av[i]*bv.z; acc[i][3] += av[i]*bv.w;
            }
        }
        __syncthreads();
    }
    float4 bb = *(const float4*)&bias[bn + tn*4];
    #pragma unroll
    for (int i = 0; i < 4; i++) {
        int row = bm + tq*4 + i;
        float4 o = make_float4(acc[i][0] + bb.x, acc[i][1] + bb.y,
                               acc[i][2] + bb.z, acc[i][3] + bb.w);
        *(float4*)&C[(size_t)row * N + bn + tn*4] = o;
    }
}

// ---------------- per-head scalar coefficients -------------------------------
// coef[n,b,h,s] = 0.0125 * f( qp[b,s,:] . Wcoef[n,:,h] + bcoef[n,h] ), f=abs for n==1
__global__ void coef_kernel(const float* __restrict__ Wcoef, const float* __restrict__ bcoef)
{
    const int bs = blockIdx.x;            // 0 .. B*S-1
    const int b = bs / S, s = bs % S;
    __shared__ float sq[D];
    for (int i = threadIdx.x; i < D; i += blockDim.x) sq[i] = g_qp[(size_t)bs * D + i];
    __syncthreads();
    const int t = threadIdx.x;
    if (t < NB * H) {
        const int n = t >> 3, h = t & 7;
        const float* w = Wcoef + (size_t)n * D * H + h;
        float acc = 0.f;
        #pragma unroll 8
        for (int d = 0; d < D; d++) acc += sq[d] * w[(size_t)d * H];
        acc += bcoef[n*H + h];
        if (n == 1) acc = fabsf(acc);
        g_coef[(((size_t)n*B + b)*H + h)*S + s] = 0.0125f * acc;   // 0.1 / sqrt(64)
    }
}

// ---------------- fused basis + coef-dot + QK^T logits ----------------------
// dyn smem: bas[10][64][65] | qs[64][65] | ks[64][65] | cf[10][64]
#define LG_SMEM ((10*64*65 + 64*65 + 64*65 + 10*64) * 4)
__global__ void logits_kernel(const float* __restrict__ xdiff)
{
    extern __shared__ float sm[];
    float* bas = sm;                       // 10 * 4160
    float* qs  = bas + 10*64*65;           // 4160
    float* ks  = qs + 64*65;               // 4160
    float* cf  = ks + 64*65;               // 640

    const int b = blockIdx.z;
    const int q0 = blockIdx.y * 64, k0 = blockIdx.x * 64;
    const int tid = threadIdx.x;

    // basis from xdiff (shared across all heads)
    for (int idx = tid; idx < 64*64; idx += 256) {
        int q = idx >> 6, k = idx & 63;
        float x = xdiff[((size_t)b*S + q0 + q) * S + k0 + k];
        float s1, c1; sincospif(x, &s1, &c1);
        float tc2 = 2.f * (1.f - 2.f*s1*s1);     // 2*cos(2*pi*x)
        float s3 = tc2*s1 + s1,  c3 = tc2*c1 - c1;
        float s5 = tc2*s3 - s1,  c5 = tc2*c3 - c1;
        float s7 = tc2*s5 - s3,  c7 = tc2*c5 - c3;
        float s9 = tc2*s7 - s5,  c9 = tc2*c7 - c5;
        int base = q*65 + k;
        bas[0*4160 + base] = x;
        bas[1*4160 + base] = -0.5f * x * x;
        bas[2*4160 + base] = s1; bas[3*4160 + base] = c1;
        bas[4*4160 + base] = s3; bas[5*4160 + base] = c3;
        bas[6*4160 + base] = s5; bas[7*4160 + base] = c5;
        bas[8*4160 + base] = s9; bas[9*4160 + base] = c9;
    }

    const int tx = tid & 15, ty = tid >> 4;
    const int qb = ty * 4, kb = tx * 4;

    for (int h = 0; h < H; h++) {
        __syncthreads();   // basis ready (h=0) / previous-iter reads done
        for (int idx = tid; idx < 64*16; idx += 256) {
            int q = idx >> 4, c = (idx & 15) * 4;
            float4 v = *(const float4*)&g_qp[((size_t)b*S + q0 + q) * D + h*DH + c];
            qs[q*65+c] = v.x; qs[q*65+c+1] = v.y; qs[q*65+c+2] = v.z; qs[q*65+c+3] = v.w;
        }
        for (int idx = tid; idx < 64*16; idx += 256) {
            int k = idx >> 4, c = (idx & 15) * 4;
            float4 v = *(const float4*)&g_kp[((size_t)b*S + k0 + k) * D + h*DH + c];
            ks[k*65+c] = v.x; ks[k*65+c+1] = v.y; ks[k*65+c+2] = v.z; ks[k*65+c+3] = v.w;
        }
        for (int idx = tid; idx < NB*64; idx += 256) {
            int n = idx >> 6, q = idx & 63;
            cf[idx] = g_coef[(((size_t)n*B + b)*H + h)*S + q0 + q];
        }
        __syncthreads();

        float accb[4][4] = {};
        #pragma unroll
        for (int n = 0; n < NB; n++) {
            float cv[4];
            #pragma unroll
            for (int i = 0; i < 4; i++) cv[i] = cf[n*64 + qb + i];
            #pragma unroll
            for (int i = 0; i < 4; i++)
                #pragma unroll
                for (int j = 0; j < 4; j++)
                    accb[i][j] += cv[i] * bas[n*4160 + (qb+i)*65 + kb + j];
        }
        float accq[4][4] = {};
        #pragma unroll 8
        for (int d = 0; d < DH; d++) {
            float av[4], bv[4];
            #pragma unroll
            for (int i = 0; i < 4; i++) av[i] = qs[(qb+i)*65 + d];
            #pragma unroll
            for (int j = 0; j < 4; j++) bv[j] = ks[(kb+j)*65 + d];
            #pragma unroll
            for (int i = 0; i < 4; i++)
                #pragma unroll
                for (int j = 0; j < 4; j++)
                    accq[i][j] += av[i] * bv[j];
        }
        #pragma unroll
        for (int i = 0; i < 4; i++) {
            size_t rowo = (((size_t)(b*H + h)*S) + q0 + qb + i) * S + k0 + kb;
            float4 o = make_float4(accb[i][0] + 0.125f*accq[i][0],
                                   accb[i][1] + 0.125f*accq[i][1],
                                   accb[i][2] + 0.125f*accq[i][2],
                                   accb[i][3] + 0.125f*accq[i][3]);
            *(float4*)&g_logits[rowo] = o;
        }
    }
}

// ---------------- row softmax: logits -> attn (written to d_out) ------------
__global__ void softmax_kernel(float* __restrict__ attn)
{
    const size_t row = blockIdx.x;                // B*H*S rows
    const float4* in = (const float4*)(g_logits + row * S);
    float4* out = (float4*)(attn + row * S);
    const int t = threadIdx.x;                    // 256
    float4 a = in[t], c = in[256 + t];
    float m = fmaxf(fmaxf(fmaxf(a.x,a.y),fmaxf(a.z,a.w)),
                    fmaxf(fmaxf(c.x,c.y),fmaxf(c.z,c.w)));
    __shared__ float red[8];
    #pragma unroll
    for (int o = 16; o > 0; o >>= 1) m = fmaxf(m, __shfl_xor_sync(0xffffffffu, m, o));
    if ((t & 31) == 0) red[t >> 5] = m;
    __syncthreads();
    m = red[0];
    #pragma unroll
    for (int i = 1; i < 8; i++) m = fmaxf(m, red[i]);

    a.x = expf(a.x - m); a.y = expf(a.y - m); a.z = expf(a.z - m); a.w = expf(a.w - m);
    c.x = expf(c.x - m); c.y = expf(c.y - m); c.z = expf(c.z - m); c.w = expf(c.w - m);
    float s = a.x + a.y + a.z + a.w + c.x + c.y + c.z + c.w;
    #pragma unroll
    for (int o = 16; o > 0; o >>= 1) s += __shfl_xor_sync(0xffffffffu, s, o);
    __syncthreads();           // red reads above complete before overwrite
    if ((t & 31) == 0) red[t >> 5] = s;
    __syncthreads();
    s = red[0];
    #pragma unroll
    for (int i = 1; i < 8; i++) s += red[i];
    float inv = 1.f / s;
    a.x *= inv; a.y *= inv; a.z *= inv; a.w *= inv;
    c.x *= inv; c.y *= inv; c.z *= inv; c.w *= inv;
    out[t] = a; out[256 + t] = c;
}

// ---------------- PV: attnv[b,q, h*64+d] = sum_k attn[b,h,q,k] * vp[b,k,h*64+d]
__global__ void pv_kernel(const float* __restrict__ attn)
{
    __shared__ float at[128*65];
    __shared__ float vs[64*64];
    const int b = blockIdx.z, h = blockIdx.y;
    const int q0 = blockIdx.x * 128;
    const int tid = threadIdx.x;
    const int tx = tid & 15, ty = tid >> 4;
    float acc[8][4] = {};
    const float* arow = attn + ((size_t)(b*H + h)*S + q0) * S;
    for (int k0 = 0; k0 < S; k0 += 64) {
        #pragma unroll
        for (int i = 0; i < 8; i++) {
            int idx = tid + i*256;
            int q = idx >> 4, c = (idx & 15) * 4;
            float4 a4 = *(const float4*)&arow[(size_t)q*S + k0 + c];
            at[q*65+c] = a4.x; at[q*65+c+1] = a4.y; at[q*65+c+2] = a4.z; at[q*65+c+3] = a4.w;
        }
        #pragma unroll
        for (int i = 0; i < 4; i++) {
            int idx = tid + i*256;
            int k = idx >> 4, c = (idx & 15) * 4;
            *(float4*)&vs[k*64 + c] =
                *(const float4*)&g_vp[((size_t)b*S + k0 + k)*D + h*DH + c];
        }
        __syncthreads();
        #pragma unroll 4
        for (int k = 0; k < 64; k++) {
            float4 v4 = *(const float4*)&vs[k*64 + tx*4];
            #pragma unroll
            for (int i = 0; i < 8; i++) {
                float a = at[(ty*8 + i)*65 + k];
                acc[i][0] += a*v4.x; acc[i][1] += a*v4.y;
                acc[i][2] += a*v4.z; acc[i][3] += a*v4.w;
            }
        }
        __syncthreads();
    }
    #pragma unroll
    for (int i = 0; i < 8; i++) {
        int q = q0 + ty*8 + i;
        *(float4*)&g_attnv[((size_t)b*S + q)*D + h*DH + tx*4] =
            make_float4(acc[i][0], acc[i][1], acc[i][2], acc[i][3]);
    }
}

// -----------------------------------------------------------------------------
extern "C" void kernel_launch(void* const* d_in, const int* in_sizes, int n_in,
                              void* d_out, int out_size)
{
    const float* q     = (const float*)d_in[0];
    const float* k     = (const float*)d_in[1];
    const float* v     = (const float*)d_in[2];
    const float* xdiff = (const float*)d_in[3];
    const float* Wq    = (const float*)d_in[4];
    const float* bq    = (const float*)d_in[5];
    const float* Wk    = (const float*)d_in[6];
    const float* bk    = (const float*)d_in[7];
    const float* Wv    = (const float*)d_in[8];
    const float* bv    = (const float*)d_in[9];
    const float* Wcoef = (const float*)d_in[10];
    const float* bcoef = (const float*)d_in[11];
    const float* Wo    = (const float*)d_in[12];
    const float* bo    = (const float*)d_in[13];
    float* out = (float*)d_out;                       // [B*S*D] out | [B*H*S*S] attn
    float* attn = out + (size_t)B*S*D;

    float *qp, *kp, *vp, *av;
    cudaGetSymbolAddress((void**)&qp, g_qp);
    cudaGetSymbolAddress((void**)&kp, g_kp);
    cudaGetSymbolAddress((void**)&vp, g_vp);
    cudaGetSymbolAddress((void**)&av, g_attnv);

    cudaFuncSetAttribute(logits_kernel, cudaFuncAttributeMaxDynamicSharedMemorySize, LG_SMEM);

    dim3 ggrid(D/64, (B*S)/64);
    gemm_bias_kernel<<<ggrid, 256>>>(q, Wq, bq, qp, B*S, D, D);
    gemm_bias_kernel<<<ggrid, 256>>>(k, Wk, bk, kp, B*S, D, D);
    gemm_bias_kernel<<<ggrid, 256>>>(v, Wv, bv, vp, B*S, D, D);

    coef_kernel<<<B*S, 128>>>(Wcoef, bcoef);

    logits_kernel<<<dim3(S/64, S/64, B), 256, LG_SMEM>>>(xdiff);

    softmax_kernel<<<B*H*S, 256>>>(attn);

    pv_kernel<<<dim3(S/128, H, B), 256>>>(attn);

    gemm_bias_kernel<<<ggrid, 256>>>(av, Wo, bo, out, B*S, D, D);
}

// round 3
// speedup vs baseline: 1.0702x; 1.0702x over previous
#include <cuda_runtime.h>
#include <mma.h>
#include <math.h>

using namespace nvcuda;

#define B 2
#define S 2048
#define D 512
#define H 8
#define DH 64
#define NB 10

// ---------------- scratch ----------------------------------------------------
__device__ float g_qp[B*S*D];
__device__ float g_kp[B*S*D];
__device__ float g_vp[B*S*D];
__device__ float g_coef[NB*B*H*S];                 // [n][b][h][s], pre-scaled by 0.1/8
__device__ float g_logits[(size_t)B*H*S*S];        // 268 MB
__device__ float g_attnv[B*S*D];                   // attn @ V, (b,s, h*64+d)

// ---------------- generic tiled GEMM:  C = A(MxK) * W(KxN) + bias ------------
__global__ void gemm_bias_kernel(const float* __restrict__ A, const float* __restrict__ W,
                                 const float* __restrict__ bias, float* __restrict__ C,
                                 int M, int N, int K)
{
    __shared__ float As[16*65];   // [k][m] padded
    __shared__ float Bs[16*64];   // [k][n]
    const int bm = blockIdx.y * 64, bn = blockIdx.x * 64;
    const int tid = threadIdx.x;
    const int tn = tid & 15, tq = tid >> 4;
    const int ar = tid >> 2, ac = (tid & 3) << 2;
    const int br = tid >> 4, bc = (tid & 15) << 2;
    float acc[4][4] = {};
    for (int k0 = 0; k0 < K; k0 += 16) {
        float4 a4 = *(const float4*)&A[(size_t)(bm + ar) * K + k0 + ac];
        As[(ac+0)*65 + ar] = a4.x; As[(ac+1)*65 + ar] = a4.y;
        As[(ac+2)*65 + ar] = a4.z; As[(ac+3)*65 + ar] = a4.w;
        float4 b4 = *(const float4*)&W[(size_t)(k0 + br) * N + bn + bc];
        *(float4*)&Bs[br*64 + bc] = b4;
        __syncthreads();
        #pragma unroll
        for (int k = 0; k < 16; k++) {
            float4 bv = *(const float4*)&Bs[k*64 + tn*4];
            float av[4];
            #pragma unroll
            for (int i = 0; i < 4; i++) av[i] = As[k*65 + tq*4 + i];
            #pragma unroll
            for (int i = 0; i < 4; i++) {
                acc[i][0] += av[i]*bv.x; acc[i][1] += av[i]*bv.y;
                acc[i][2] += av[i]*bv.z; acc[i][3] += av[i]*bv.w;
            }
        }
        __syncthreads();
    }
    float4 bb = *(const float4*)&bias[bn + tn*4];
    #pragma unroll
    for (int i = 0; i < 4; i++) {
        int row = bm + tq*4 + i;
        float4 o = make_float4(acc[i][0] + bb.x, acc[i][1] + bb.y,
                               acc[i][2] + bb.z, acc[i][3] + bb.w);
        *(float4*)&C[(size_t)row * N + bn + tn*4] = o;
    }
}

// ---------------- coef as tiled GEMM: (B*S x 512) @ (512 x 80) ---------------
// C[r][nh] = qp[r][:] . Wcoef[:, nh]   with Wcoef (n,d,h) layout.
__global__ void coef_kernel(const float* __restrict__ Wcoef, const float* __restrict__ bcoef)
{
    __shared__ float qsm[64*33];
    __shared__ float wsm[32*80];
    const int bm = blockIdx.x * 64;
    const int t = threadIdx.x;
    const int r = t & 63;             // row within tile
    const int cg = t >> 6;            // col group: 20 cols each
    float acc[20] = {};
    for (int k0 = 0; k0 < D; k0 += 32) {
        #pragma unroll
        for (int i = 0; i < 8; i++) {
            int idx = i*256 + t;
            int rr = idx >> 5, cc = idx & 31;
            qsm[rr*33 + cc] = g_qp[(size_t)(bm + rr) * D + k0 + cc];
        }
        #pragma unroll
        for (int i = 0; i < 10; i++) {
            int idx = i*256 + t;
            int kk = idx / 80, nh = idx % 80;
            wsm[kk*80 + nh] = Wcoef[(size_t)(nh >> 3) * D * H + (size_t)(k0 + kk) * H + (nh & 7)];
        }
        __syncthreads();
        #pragma unroll 8
        for (int kk = 0; kk < 32; kk++) {
            float a = qsm[r*33 + kk];
            #pragma unroll
            for (int j = 0; j < 5; j++) {
                float4 w4 = *(const float4*)&wsm[kk*80 + cg*20 + j*4];
                acc[j*4+0] += a*w4.x; acc[j*4+1] += a*w4.y;
                acc[j*4+2] += a*w4.z; acc[j*4+3] += a*w4.w;
            }
        }
        __syncthreads();
    }
    const int rg = bm + r;
    const int b = rg >> 11, s = rg & (S-1);
    #pragma unroll
    for (int j = 0; j < 20; j++) {
        int nh = cg*20 + j;
        int n = nh >> 3, h = nh & 7;
        float v = acc[j] + bcoef[nh];
        if (n == 1) v = fabsf(v);
        g_coef[(((size_t)n*B + b)*H + h)*S + s] = 0.0125f * v;   // 0.1 / sqrt(64)
    }
}

// ---------------- fused basis + coef-dot + QK^T (wmma tf32) ------------------
// smem: bas[10][64][66] | qs[64][68] | ks[64][68] | ct[64][68] | cf[10][64]
#define BAS_LD 66
#define QK_LD  68
#define LG_SMEM ((10*64*BAS_LD + 3*64*QK_LD + NB*64) * 4)
__global__ void logits_kernel(const float* __restrict__ xdiff)
{
    extern __shared__ float sm[];
    float* bas = sm;                          // 10 * 64*66
    float* qs  = bas + 10*64*BAS_LD;          // 64*68 (pre-scaled by 0.125)
    float* ks  = qs + 64*QK_LD;               // 64*68
    float* ct  = ks + 64*QK_LD;               // 64*68 basis-init / C tile
    float* cf  = ct + 64*QK_LD;               // 10*64

    const int b = blockIdx.z;
    const int q0 = blockIdx.y * 64, k0 = blockIdx.x * 64;
    const int tid = threadIdx.x;
    const int w = tid >> 5;
    const int wr = w >> 1, wc = w & 1;        // 4x2 warp grid over 64x64

    // basis from xdiff (shared across all heads)
    for (int idx = tid; idx < 64*64; idx += 256) {
        int q = idx >> 6, k = idx & 63;
        float x = xdiff[((size_t)b*S + q0 + q) * S + k0 + k];
        float s1, c1; sincospif(x, &s1, &c1);
        float tc2 = 2.f * (1.f - 2.f*s1*s1);     // 2*cos(2*pi*x)
        float s3 = tc2*s1 + s1,  c3 = tc2*c1 - c1;
        float s5 = tc2*s3 - s1,  c5 = tc2*c3 - c1;
        float s7 = tc2*s5 - s3,  c7 = tc2*c5 - c3;
        float s9 = tc2*s7 - s5,  c9 = tc2*c7 - c5;
        int base = q*BAS_LD + k;
        bas[0*64*BAS_LD + base] = x;
        bas[1*64*BAS_LD + base] = -0.5f * x * x;
        bas[2*64*BAS_LD + base] = s1; bas[3*64*BAS_LD + base] = c1;
        bas[4*64*BAS_LD + base] = s3; bas[5*64*BAS_LD + base] = c3;
        bas[6*64*BAS_LD + base] = s5; bas[7*64*BAS_LD + base] = c5;
        bas[8*64*BAS_LD + base] = s9; bas[9*64*BAS_LD + base] = c9;
    }

    const int dq = tid >> 2;              // basis-dot: row
    const int dk = (tid & 3) * 16;        // basis-dot: 16-wide k strip

    for (int h = 0; h < H; h++) {
        __syncthreads();   // basis ready (h=0) / previous-iter smem reads done
        for (int idx = tid; idx < 64*16; idx += 256) {
            int q = idx >> 4, c = (idx & 15) * 4;
            float4 v = *(const float4*)&g_qp[((size_t)b*S + q0 + q) * D + h*DH + c];
            qs[q*QK_LD+c]   = 0.125f*v.x; qs[q*QK_LD+c+1] = 0.125f*v.y;
            qs[q*QK_LD+c+2] = 0.125f*v.z; qs[q*QK_LD+c+3] = 0.125f*v.w;
        }
        for (int idx = tid; idx < 64*16; idx += 256) {
            int k = idx >> 4, c = (idx & 15) * 4;
            float4 v = *(const float4*)&g_kp[((size_t)b*S + k0 + k) * D + h*DH + c];
            ks[k*QK_LD+c] = v.x; ks[k*QK_LD+c+1] = v.y;
            ks[k*QK_LD+c+2] = v.z; ks[k*QK_LD+c+3] = v.w;
        }
        for (int idx = tid; idx < NB*64; idx += 256) {
            int n = idx >> 6, q = idx & 63;
            cf[idx] = g_coef[(((size_t)n*B + b)*H + h)*S + q0 + q];
        }
        __syncthreads();

        // basis-dot into ct (exact fp32)
        {
            float acc[16] = {};
            #pragma unroll
            for (int n = 0; n < NB; n++) {
                float c = cf[n*64 + dq];
                const float* bp = &bas[n*64*BAS_LD + dq*BAS_LD + dk];
                #pragma unroll
                for (int j = 0; j < 8; j++) {
                    float2 bv = *(const float2*)&bp[2*j];
                    acc[2*j]   += c * bv.x;
                    acc[2*j+1] += c * bv.y;
                }
            }
            #pragma unroll
            for (int i = 0; i < 4; i++)
                *(float4*)&ct[dq*QK_LD + dk + 4*i] =
                    make_float4(acc[4*i], acc[4*i+1], acc[4*i+2], acc[4*i+3]);
        }
        __syncthreads();

        // wmma: C(16x32 per warp) = basis_init + (0.125*Q) K^T
        wmma::fragment<wmma::accumulator, 16,16,8, float> c0, c1;
        wmma::load_matrix_sync(c0, ct + wr*16*QK_LD + wc*32,      QK_LD, wmma::mem_row_major);
        wmma::load_matrix_sync(c1, ct + wr*16*QK_LD + wc*32 + 16, QK_LD, wmma::mem_row_major);
        #pragma unroll
        for (int d0 = 0; d0 < DH; d0 += 8) {
            wmma::fragment<wmma::matrix_a, 16,16,8, wmma::precision::tf32, wmma::row_major> af;
            wmma::fragment<wmma::matrix_b, 16,16,8, wmma::precision::tf32, wmma::col_major> b0, b1;
            wmma::load_matrix_sync(af, qs + wr*16*QK_LD + d0, QK_LD);
            wmma::load_matrix_sync(b0, ks + (wc*32)*QK_LD + d0, QK_LD);
            wmma::load_matrix_sync(b1, ks + (wc*32+16)*QK_LD + d0, QK_LD);
            #pragma unroll
            for (int i = 0; i < af.num_elements; i++) af.x[i] = wmma::__float_to_tf32(af.x[i]);
            #pragma unroll
            for (int i = 0; i < b0.num_elements; i++) b0.x[i] = wmma::__float_to_tf32(b0.x[i]);
            #pragma unroll
            for (int i = 0; i < b1.num_elements; i++) b1.x[i] = wmma::__float_to_tf32(b1.x[i]);
            wmma::mma_sync(c0, af, b0, c0);
            wmma::mma_sync(c1, af, b1, c1);
        }
        float* orow = &g_logits[(((size_t)(b*H + h)*S) + q0 + wr*16) * S + k0 + wc*32];
        wmma::store_matrix_sync(orow,      c0, S, wmma::mem_row_major);
        wmma::store_matrix_sync(orow + 16, c1, S, wmma::mem_row_major);
    }
}

// ---------------- row softmax: logits -> attn (written to d_out) ------------
__global__ void softmax_kernel(float* __restrict__ attn)
{
    const size_t row = blockIdx.x;                // B*H*S rows
    const float4* in = (const float4*)(g_logits + row * S);
    float4* out = (float4*)(attn + row * S);
    const int t = threadIdx.x;                    // 256
    float4 a = in[t], c = in[256 + t];
    float m = fmaxf(fmaxf(fmaxf(a.x,a.y),fmaxf(a.z,a.w)),
                    fmaxf(fmaxf(c.x,c.y),fmaxf(c.z,c.w)));
    __shared__ float red[8];
    #pragma unroll
    for (int o = 16; o > 0; o >>= 1) m = fmaxf(m, __shfl_xor_sync(0xffffffffu, m, o));
    if ((t & 31) == 0) red[t >> 5] = m;
    __syncthreads();
    m = red[0];
    #pragma unroll
    for (int i = 1; i < 8; i++) m = fmaxf(m, red[i]);

    a.x = __expf(a.x - m); a.y = __expf(a.y - m); a.z = __expf(a.z - m); a.w = __expf(a.w - m);
    c.x = __expf(c.x - m); c.y = __expf(c.y - m); c.z = __expf(c.z - m); c.w = __expf(c.w - m);
    float s = a.x + a.y + a.z + a.w + c.x + c.y + c.z + c.w;
    #pragma unroll
    for (int o = 16; o > 0; o >>= 1) s += __shfl_xor_sync(0xffffffffu, s, o);
    __syncthreads();           // red reads above complete before overwrite
    if ((t & 31) == 0) red[t >> 5] = s;
    __syncthreads();
    s = red[0];
    #pragma unroll
    for (int i = 1; i < 8; i++) s += red[i];
    float inv = 1.f / s;
    a.x *= inv; a.y *= inv; a.z *= inv; a.w *= inv;
    c.x *= inv; c.y *= inv; c.z *= inv; c.w *= inv;
    out[t] = a; out[256 + t] = c;
}

// ---------------- PV (wmma tf32): attnv = attn @ V ---------------------------
// block: 128 q-rows x 64 d-cols for one (b,h); k-tiles of 64
#define PV_LD 68
__global__ void pv_kernel(const float* __restrict__ attn)
{
    __shared__ float at[128*PV_LD];
    __shared__ float vs[64*PV_LD];
    const int b = blockIdx.z, h = blockIdx.y;
    const int q0 = blockIdx.x * 128;
    const int tid = threadIdx.x;
    const int w = tid >> 5;                   // warp -> 16 q-rows
    const float* arow = attn + ((size_t)(b*H + h)*S + q0) * S;

    wmma::fragment<wmma::accumulator, 16,16,8, float> cfr[4];
    #pragma unroll
    for (int i = 0; i < 4; i++) wmma::fill_fragment(cfr[i], 0.f);

    for (int k0 = 0; k0 < S; k0 += 64) {
        #pragma unroll
        for (int i = 0; i < 8; i++) {
            int idx = i*256 + tid;
            int q = idx >> 4, c = (idx & 15) * 4;
            float4 a4 = *(const float4*)&arow[(size_t)q*S + k0 + c];
            *(float4*)&at[q*PV_LD + c] = a4;
        }
        #pragma unroll
        for (int i = 0; i < 4; i++) {
            int idx = i*256 + tid;
            int k = idx >> 4, c = (idx & 15) * 4;
            *(float4*)&vs[k*PV_LD + c] =
                *(const float4*)&g_vp[((size_t)b*S + k0 + k)*D + h*DH + c];
        }
        __syncthreads();
        #pragma unroll
        for (int ch = 0; ch < 8; ch++) {
            wmma::fragment<wmma::matrix_a, 16,16,8, wmma::precision::tf32, wmma::row_major> af;
            wmma::load_matrix_sync(af, at + w*16*PV_LD + ch*8, PV_LD);
            #pragma unroll
            for (int i = 0; i < af.num_elements; i++) af.x[i] = wmma::__float_to_tf32(af.x[i]);
            #pragma unroll
            for (int nb = 0; nb < 4; nb++) {
                wmma::fragment<wmma::matrix_b, 16,16,8, wmma::precision::tf32, wmma::row_major> bf;
                wmma::load_matrix_sync(bf, vs + (ch*8)*PV_LD + nb*16, PV_LD);
                #pragma unroll
                for (int i = 0; i < bf.num_elements; i++) bf.x[i] = wmma::__float_to_tf32(bf.x[i]);
                wmma::mma_sync(cfr[nb], af, bf, cfr[nb]);
            }
        }
        __syncthreads();
    }
    #pragma unroll
    for (int nb = 0; nb < 4; nb++) {
        float* o = &g_attnv[((size_t)b*S + q0 + w*16)*D + h*DH + nb*16];
        wmma::store_matrix_sync(o, cfr[nb], D, wmma::mem_row_major);
    }
}

// -----------------------------------------------------------------------------
extern "C" void kernel_launch(void* const* d_in, const int* in_sizes, int n_in,
                              void* d_out, int out_size)
{
    const float* q     = (const float*)d_in[0];
    const float* k     = (const float*)d_in[1];
    const float* v     = (const float*)d_in[2];
    const float* xdiff = (const float*)d_in[3];
    const float* Wq    = (const float*)d_in[4];
    const float* bq    = (const float*)d_in[5];
    const float* Wk    = (const float*)d_in[6];
    const float* bk    = (const float*)d_in[7];
    const float* Wv    = (const float*)d_in[8];
    const float* bv    = (const float*)d_in[9];
    const float* Wcoef = (const float*)d_in[10];
    const float* bcoef = (const float*)d_in[11];
    const float* Wo    = (const float*)d_in[12];
    const float* bo    = (const float*)d_in[13];
    float* out = (float*)d_out;                       // [B*S*D] out | [B*H*S*S] attn
    float* attn = out + (size_t)B*S*D;

    float *qp, *kp, *vp, *av;
    cudaGetSymbolAddress((void**)&qp, g_qp);
    cudaGetSymbolAddress((void**)&kp, g_kp);
    cudaGetSymbolAddress((void**)&vp, g_vp);
    cudaGetSymbolAddress((void**)&av, g_attnv);

    cudaFuncSetAttribute(logits_kernel, cudaFuncAttributeMaxDynamicSharedMemorySize, LG_SMEM);

    dim3 ggrid(D/64, (B*S)/64);
    gemm_bias_kernel<<<ggrid, 256>>>(q, Wq, bq, qp, B*S, D, D);
    gemm_bias_kernel<<<ggrid, 256>>>(k, Wk, bk, kp, B*S, D, D);
    gemm_bias_kernel<<<ggrid, 256>>>(v, Wv, bv, vp, B*S, D, D);

    coef_kernel<<<(B*S)/64, 256>>>(Wcoef, bcoef);

    logits_kernel<<<dim3(S/64, S/64, B), 256, LG_SMEM>>>(xdiff);

    softmax_kernel<<<B*H*S, 256>>>(attn);

    pv_kernel<<<dim3(S/128, H, B), 256>>>(attn);

    gemm_bias_kernel<<<ggrid, 256>>>(av, Wo, bo, out, B*S, D, D);
}

// round 4
// speedup vs baseline: 1.6542x; 1.5458x over previous
#include <cuda_runtime.h>
#include <mma.h>
#include <math.h>

using namespace nvcuda;

#define B 2
#define S 2048
#define D 512
#define H 8
#define DH 64
#define NB 10
#define PI_F 3.14159265358979323846f

// ---------------- scratch ----------------------------------------------------
__device__ float g_qp[B*S*D];
__device__ float g_kp[B*S*D];
__device__ float g_vp[B*S*D];
__device__ float g_coef[NB*B*H*S];                 // [n][b][h][s], pre-scaled by 0.1/8
__device__ float g_logits[(size_t)B*H*S*S];        // 268 MB
__device__ float g_attnv[B*S*D];                   // attn @ V, (b,s, h*64+d)

// ---------------- tf32 wmma GEMM:  C = A(MxK) @ W(KxN) + bias ----------------
// block tile 128x128, K-chunks of 32. 8 warps in 4x2; warp tile 32x64.
#define GT_ALD 36
#define GT_WLD 132
__global__ __launch_bounds__(256) void gemm_bias_tc(
    const float* __restrict__ A, const float* __restrict__ W,
    const float* __restrict__ bias, float* __restrict__ C,
    int M, int N, int K)
{
    __shared__ float As[128*GT_ALD];   // [m][k]
    __shared__ float Ws[32*GT_WLD];    // [k][n]
    __shared__ float Bt[16*GT_WLD];    // bias tile (rows identical)
    const int bm = blockIdx.y * 128, bn = blockIdx.x * 128;
    const int tid = threadIdx.x, w = tid >> 5;
    const int wm = (w >> 1) * 32, wn = (w & 1) * 64;

    for (int i = tid; i < 16*128; i += 256) {
        int r = i >> 7, c = i & 127;
        Bt[r*GT_WLD + c] = bias[bn + c];
    }
    __syncthreads();

    wmma::fragment<wmma::accumulator, 16,16,8, float> acc[2][4];
    #pragma unroll
    for (int i = 0; i < 2; i++)
        #pragma unroll
        for (int j = 0; j < 4; j++)
            wmma::load_matrix_sync(acc[i][j], Bt + wn + j*16, GT_WLD, wmma::mem_row_major);

    for (int k0 = 0; k0 < K; k0 += 32) {
        #pragma unroll
        for (int i = 0; i < 4; i++) {
            int id = i*256 + tid;
            int row = id >> 3, kc = (id & 7) * 4;
            float4 v = *(const float4*)&A[(size_t)(bm + row) * K + k0 + kc];
            *(float4*)&As[row*GT_ALD + kc] = v;
        }
        #pragma unroll
        for (int i = 0; i < 4; i++) {
            int id = i*256 + tid;
            int kr = id >> 5, nc = (id & 31) * 4;
            float4 v = *(const float4*)&W[(size_t)(k0 + kr) * N + bn + nc];
            *(float4*)&Ws[kr*GT_WLD + nc] = v;
        }
        __syncthreads();
        #pragma unroll
        for (int ks = 0; ks < 4; ks++) {
            wmma::fragment<wmma::matrix_a, 16,16,8, wmma::precision::tf32, wmma::row_major> a0, a1;
            wmma::load_matrix_sync(a0, As + wm*GT_ALD + ks*8, GT_ALD);
            wmma::load_matrix_sync(a1, As + (wm+16)*GT_ALD + ks*8, GT_ALD);
            #pragma unroll
            for (int i = 0; i < a0.num_elements; i++) {
                a0.x[i] = wmma::__float_to_tf32(a0.x[i]);
                a1.x[i] = wmma::__float_to_tf32(a1.x[i]);
            }
            #pragma unroll
            for (int j = 0; j < 4; j++) {
                wmma::fragment<wmma::matrix_b, 16,16,8, wmma::precision::tf32, wmma::row_major> bf;
                wmma::load_matrix_sync(bf, Ws + (ks*8)*GT_WLD + wn + j*16, GT_WLD);
                #pragma unroll
                for (int i = 0; i < bf.num_elements; i++) bf.x[i] = wmma::__float_to_tf32(bf.x[i]);
                wmma::mma_sync(acc[0][j], a0, bf, acc[0][j]);
                wmma::mma_sync(acc[1][j], a1, bf, acc[1][j]);
            }
        }
        __syncthreads();
    }
    #pragma unroll
    for (int i = 0; i < 2; i++)
        #pragma unroll
        for (int j = 0; j < 4; j++)
            wmma::store_matrix_sync(C + (size_t)(bm + wm + i*16) * N + bn + wn + j*16,
                                    acc[i][j], N, wmma::mem_row_major);
}

// ---------------- coef: (B*S x 512) @ (512 x 80) ------------------------------
__global__ void coef_kernel(const float* __restrict__ Wcoef, const float* __restrict__ bcoef)
{
    __shared__ float qsm[32*33];
    __shared__ float wsm[32*80];
    const int bm = blockIdx.x * 32;
    const int t = threadIdx.x;
    const int r = t & 31;             // row within tile
    const int cg = t >> 5;            // col group: 10 cols each
    float acc[10] = {};
    for (int k0 = 0; k0 < D; k0 += 32) {
        #pragma unroll
        for (int i = 0; i < 4; i++) {
            int idx = i*256 + t;
            int rr = idx >> 5, cc = idx & 31;
            qsm[rr*33 + cc] = g_qp[(size_t)(bm + rr) * D + k0 + cc];
        }
        #pragma unroll
        for (int i = 0; i < 10; i++) {
            int idx = i*256 + t;
            int kk = idx / 80, nh = idx % 80;
            wsm[kk*80 + nh] = Wcoef[(size_t)(nh >> 3) * D * H + (size_t)(k0 + kk) * H + (nh & 7)];
        }
        __syncthreads();
        #pragma unroll 8
        for (int kk = 0; kk < 32; kk++) {
            float a = qsm[r*33 + kk];
            #pragma unroll
            for (int j = 0; j < 5; j++) {
                float2 w2 = *(const float2*)&wsm[kk*80 + cg*10 + j*2];
                acc[j*2+0] += a*w2.x; acc[j*2+1] += a*w2.y;
            }
        }
        __syncthreads();
    }
    const int rg = bm + r;
    const int b = rg >> 11, s = rg & (S-1);
    #pragma unroll
    for (int j = 0; j < 10; j++) {
        int nh = cg*10 + j;
        int n = nh >> 3, h = nh & 7;
        float v = acc[j] + bcoef[nh];
        if (n == 1) v = fabsf(v);
        g_coef[(((size_t)n*B + b)*H + h)*S + s] = 0.0125f * v;   // 0.1 / sqrt(64)
    }
}

// ---------------- fused basis + coef-dot + QK^T (wmma tf32) ------------------
// Basis kept in registers (x, sin, cos per cell); per-head Chebyshev ladder +
// 10-term dot writes the wmma C-init tile. smem: qs|ks|ct (64x68) + cf (10x64).
#define QK_LD  68
#define LG_SMEM ((3*64*QK_LD + NB*64) * 4)
__global__ __launch_bounds__(256, 2) void logits_kernel(const float* __restrict__ xdiff)
{
    extern __shared__ float sm[];
    float* qs  = sm;                          // 64*68 (pre-scaled by 0.125)
    float* ks  = qs + 64*QK_LD;               // 64*68
    float* ct  = ks + 64*QK_LD;               // 64*68 basis-init / C tile
    float* cf  = ct + 64*QK_LD;               // 10*64

    const int b = blockIdx.z;
    const int q0 = blockIdx.y * 64, k0 = blockIdx.x * 64;
    const int tid = threadIdx.x;
    const int w = tid >> 5;
    const int wr = w >> 1, wc = w & 1;        // 4x2 warp grid over 64x64

    // each thread owns 16 cells: row dq, k strip of 16
    const int dq = tid >> 2;
    const int dk = (tid & 3) * 16;

    float xr[16], sr[16], cr[16];
    {
        const float* xp = &xdiff[((size_t)b*S + q0 + dq) * S + k0 + dk];
        #pragma unroll
        for (int j4 = 0; j4 < 4; j4++) {
            float4 x4 = *(const float4*)&xp[j4*4];
            float xv[4] = {x4.x, x4.y, x4.z, x4.w};
            #pragma unroll
            for (int u = 0; u < 4; u++) {
                int j = j4*4 + u;
                float x = xv[u];
                float t = fmaf(-2.f, rintf(0.5f * x), x);   // reduce to [-1,1], period 2
                float s1, c1;
                __sincosf(PI_F * t, &s1, &c1);
                xr[j] = x; sr[j] = s1; cr[j] = c1;
            }
        }
    }

    for (int h = 0; h < H; h++) {
        __syncthreads();   // previous iteration's smem reads complete
        for (int idx = tid; idx < 64*16; idx += 256) {
            int q = idx >> 4, c = (idx & 15) * 4;
            float4 v = *(const float4*)&g_qp[((size_t)b*S + q0 + q) * D + h*DH + c];
            qs[q*QK_LD+c]   = 0.125f*v.x; qs[q*QK_LD+c+1] = 0.125f*v.y;
            qs[q*QK_LD+c+2] = 0.125f*v.z; qs[q*QK_LD+c+3] = 0.125f*v.w;
        }
        for (int idx = tid; idx < 64*16; idx += 256) {
            int k = idx >> 4, c = (idx & 15) * 4;
            float4 v = *(const float4*)&g_kp[((size_t)b*S + k0 + k) * D + h*DH + c];
            ks[k*QK_LD+c] = v.x; ks[k*QK_LD+c+1] = v.y;
            ks[k*QK_LD+c+2] = v.z; ks[k*QK_LD+c+3] = v.w;
        }
        for (int idx = tid; idx < NB*64; idx += 256) {
            int n = idx >> 6, q = idx & 63;
            cf[idx] = g_coef[(((size_t)n*B + b)*H + h)*S + q0 + q];
        }
        __syncthreads();

        // per-cell Chebyshev ladder + 10-term dot -> ct (exact fp32)
        {
            float c0 = cf[0*64 + dq], c1f = cf[1*64 + dq];
            float c2 = cf[2*64 + dq], c3 = cf[3*64 + dq];
            float c4 = cf[4*64 + dq], c5 = cf[5*64 + dq];
            float c6 = cf[6*64 + dq], c7 = cf[7*64 + dq];
            float c8 = cf[8*64 + dq], c9 = cf[9*64 + dq];
            #pragma unroll
            for (int j4 = 0; j4 < 4; j4++) {
                float o[4];
                #pragma unroll
                for (int u = 0; u < 4; u++) {
                    int j = j4*4 + u;
                    float x = xr[j], s1 = sr[j], cc1 = cr[j];
                    float tc2 = 2.f * fmaf(-2.f*s1, s1, 1.f);      // 2*cos(2*pi*x)
                    float s3 = fmaf(tc2, s1,  s1),  cc3 = fmaf(tc2, cc1, -cc1);
                    float s5 = fmaf(tc2, s3, -s1),  cc5 = fmaf(tc2, cc3, -cc1);
                    float s7 = fmaf(tc2, s5, -s3),  cc7 = fmaf(tc2, cc5, -cc3);
                    float s9 = fmaf(tc2, s7, -s5),  cc9 = fmaf(tc2, cc7, -cc5);
                    float a = c0 * x;
                    a = fmaf(c1f, -0.5f*x*x, a);
                    a = fmaf(c2, s1, a);  a = fmaf(c3, cc1, a);
                    a = fmaf(c4, s3, a);  a = fmaf(c5, cc3, a);
                    a = fmaf(c6, s5, a);  a = fmaf(c7, cc5, a);
                    a = fmaf(c8, s9, a);  a = fmaf(c9, cc9, a);
                    o[u] = a;
                }
                *(float4*)&ct[dq*QK_LD + dk + j4*4] = make_float4(o[0], o[1], o[2], o[3]);
            }
        }
        __syncthreads();

        // wmma: C(16x32 per warp) = basis_init + (0.125*Q) K^T
        wmma::fragment<wmma::accumulator, 16,16,8, float> c0, c1;
        wmma::load_matrix_sync(c0, ct + wr*16*QK_LD + wc*32,      QK_LD, wmma::mem_row_major);
        wmma::load_matrix_sync(c1, ct + wr*16*QK_LD + wc*32 + 16, QK_LD, wmma::mem_row_major);
        #pragma unroll
        for (int d0 = 0; d0 < DH; d0 += 8) {
            wmma::fragment<wmma::matrix_a, 16,16,8, wmma::precision::tf32, wmma::row_major> af;
            wmma::fragment<wmma::matrix_b, 16,16,8, wmma::precision::tf32, wmma::col_major> b0, b1;
            wmma::load_matrix_sync(af, qs + wr*16*QK_LD + d0, QK_LD);
            wmma::load_matrix_sync(b0, ks + (wc*32)*QK_LD + d0, QK_LD);
            wmma::load_matrix_sync(b1, ks + (wc*32+16)*QK_LD + d0, QK_LD);
            #pragma unroll
            for (int i = 0; i < af.num_elements; i++) af.x[i] = wmma::__float_to_tf32(af.x[i]);
            #pragma unroll
            for (int i = 0; i < b0.num_elements; i++) b0.x[i] = wmma::__float_to_tf32(b0.x[i]);
            #pragma unroll
            for (int i = 0; i < b1.num_elements; i++) b1.x[i] = wmma::__float_to_tf32(b1.x[i]);
            wmma::mma_sync(c0, af, b0, c0);
            wmma::mma_sync(c1, af, b1, c1);
        }
        float* orow = &g_logits[(((size_t)(b*H + h)*S) + q0 + wr*16) * S + k0 + wc*32];
        wmma::store_matrix_sync(orow,      c0, S, wmma::mem_row_major);
        wmma::store_matrix_sync(orow + 16, c1, S, wmma::mem_row_major);
    }
}

// ---------------- row softmax: logits -> attn (written to d_out) ------------
__global__ void softmax_kernel(float* __restrict__ attn)
{
    const size_t row = blockIdx.x;                // B*H*S rows
    const float4* in = (const float4*)(g_logits + row * S);
    float4* out = (float4*)(attn + row * S);
    const int t = threadIdx.x;                    // 256
    float4 a = in[t], c = in[256 + t];
    float m = fmaxf(fmaxf(fmaxf(a.x,a.y),fmaxf(a.z,a.w)),
                    fmaxf(fmaxf(c.x,c.y),fmaxf(c.z,c.w)));
    __shared__ float red[8];
    #pragma unroll
    for (int o = 16; o > 0; o >>= 1) m = fmaxf(m, __shfl_xor_sync(0xffffffffu, m, o));
    if ((t & 31) == 0) red[t >> 5] = m;
    __syncthreads();
    m = red[0];
    #pragma unroll
    for (int i = 1; i < 8; i++) m = fmaxf(m, red[i]);

    a.x = __expf(a.x - m); a.y = __expf(a.y - m); a.z = __expf(a.z - m); a.w = __expf(a.w - m);
    c.x = __expf(c.x - m); c.y = __expf(c.y - m); c.z = __expf(c.z - m); c.w = __expf(c.w - m);
    float s = a.x + a.y + a.z + a.w + c.x + c.y + c.z + c.w;
    #pragma unroll
    for (int o = 16; o > 0; o >>= 1) s += __shfl_xor_sync(0xffffffffu, s, o);
    __syncthreads();           // red reads above complete before overwrite
    if ((t & 31) == 0) red[t >> 5] = s;
    __syncthreads();
    s = red[0];
    #pragma unroll
    for (int i = 1; i < 8; i++) s += red[i];
    float inv = 1.f / s;
    a.x *= inv; a.y *= inv; a.z *= inv; a.w *= inv;
    c.x *= inv; c.y *= inv; c.z *= inv; c.w *= inv;
    out[t] = a; out[256 + t] = c;
}

// ---------------- PV (wmma tf32): attnv = attn @ V ---------------------------
#define PV_LD 68
__global__ void pv_kernel(const float* __restrict__ attn)
{
    __shared__ float at[128*PV_LD];
    __shared__ float vs[64*PV_LD];
    const int b = blockIdx.z, h = blockIdx.y;
    const int q0 = blockIdx.x * 128;
    const int tid = threadIdx.x;
    const int w = tid >> 5;                   // warp -> 16 q-rows
    const float* arow = attn + ((size_t)(b*H + h)*S + q0) * S;

    wmma::fragment<wmma::accumulator, 16,16,8, float> cfr[4];
    #pragma unroll
    for (int i = 0; i < 4; i++) wmma::fill_fragment(cfr[i], 0.f);

    for (int k0 = 0; k0 < S; k0 += 64) {
        #pragma unroll
        for (int i = 0; i < 8; i++) {
            int idx = i*256 + tid;
            int q = idx >> 4, c = (idx & 15) * 4;
            float4 a4 = *(const float4*)&arow[(size_t)q*S + k0 + c];
            *(float4*)&at[q*PV_LD + c] = a4;
        }
        #pragma unroll
        for (int i = 0; i < 4; i++) {
            int idx = i*256 + tid;
            int k = idx >> 4, c = (idx & 15) * 4;
            *(float4*)&vs[k*PV_LD + c] =
                *(const float4*)&g_vp[((size_t)b*S + k0 + k)*D + h*DH + c];
        }
        __syncthreads();
        #pragma unroll
        for (int ch = 0; ch < 8; ch++) {
            wmma::fragment<wmma::matrix_a, 16,16,8, wmma::precision::tf32, wmma::row_major> af;
            wmma::load_matrix_sync(af, at + w*16*PV_LD + ch*8, PV_LD);
            #pragma unroll
            for (int i = 0; i < af.num_elements; i++) af.x[i] = wmma::__float_to_tf32(af.x[i]);
            #pragma unroll
            for (int nb = 0; nb < 4; nb++) {
                wmma::fragment<wmma::matrix_b, 16,16,8, wmma::precision::tf32, wmma::row_major> bf;
                wmma::load_matrix_sync(bf, vs + (ch*8)*PV_LD + nb*16, PV_LD);
                #pragma unroll
                for (int i = 0; i < bf.num_elements; i++) bf.x[i] = wmma::__float_to_tf32(bf.x[i]);
                wmma::mma_sync(cfr[nb], af, bf, cfr[nb]);
            }
        }
        __syncthreads();
    }
    #pragma unroll
    for (int nb = 0; nb < 4; nb++) {
        float* o = &g_attnv[((size_t)b*S + q0 + w*16)*D + h*DH + nb*16];
        wmma::store_matrix_sync(o, cfr[nb], D, wmma::mem_row_major);
    }
}

// -----------------------------------------------------------------------------
extern "C" void kernel_launch(void* const* d_in, const int* in_sizes, int n_in,
                              void* d_out, int out_size)
{
    const float* q     = (const float*)d_in[0];
    const float* k     = (const float*)d_in[1];
    const float* v     = (const float*)d_in[2];
    const float* xdiff = (const float*)d_in[3];
    const float* Wq    = (const float*)d_in[4];
    const float* bq    = (const float*)d_in[5];
    const float* Wk    = (const float*)d_in[6];
    const float* bk    = (const float*)d_in[7];
    const float* Wv    = (const float*)d_in[8];
    const float* bv    = (const float*)d_in[9];
    const float* Wcoef = (const float*)d_in[10];
    const float* bcoef = (const float*)d_in[11];
    const float* Wo    = (const float*)d_in[12];
    const float* bo    = (const float*)d_in[13];
    float* out = (float*)d_out;                       // [B*S*D] out | [B*H*S*S] attn
    float* attn = out + (size_t)B*S*D;

    float *qp, *kp, *vp, *av;
    cudaGetSymbolAddress((void**)&qp, g_qp);
    cudaGetSymbolAddress((void**)&kp, g_kp);
    cudaGetSymbolAddress((void**)&vp, g_vp);
    cudaGetSymbolAddress((void**)&av, g_attnv);

    cudaFuncSetAttribute(logits_kernel, cudaFuncAttributeMaxDynamicSharedMemorySize, LG_SMEM);

    dim3 ggrid(D/128, (B*S)/128);
    gemm_bias_tc<<<ggrid, 256>>>(q, Wq, bq, qp, B*S, D, D);
    gemm_bias_tc<<<ggrid, 256>>>(k, Wk, bk, kp, B*S, D, D);
    gemm_bias_tc<<<ggrid, 256>>>(v, Wv, bv, vp, B*S, D, D);

    coef_kernel<<<(B*S)/32, 256>>>(Wcoef, bcoef);

    logits_kernel<<<dim3(S/64, S/64, B), 256, LG_SMEM>>>(xdiff);

    softmax_kernel<<<B*H*S, 256>>>(attn);

    pv_kernel<<<dim3(S/128, H, B), 256>>>(attn);

    gemm_bias_tc<<<ggrid, 256>>>(av, Wo, bo, out, B*S, D, D);
}